// round 12
// baseline (speedup 1.0000x reference)
#include <cuda_runtime.h>
#include <cuda_bf16.h>
#include <math_constants.h>
#include <cfloat>
#include <cstdint>

#define D_MODEL 1024
#define NHEADS  16
#define DHEAD   64
#define BATCH   2
#define SEQ     2048
#define ROWS    (BATCH * SEQ)   // 4096
#define NBH     (BATCH * NHEADS)
#define QSCALE  0.18033688011112042f   // 0.125 * log2(e)

// 2-slot operands. GEMM A/B layout: [row][chunk32][hi 32 | lo 32], row stride 2048.
__device__ __nv_bfloat16 g_Xs2[ROWS * 2048];
__device__ __nv_bfloat16 g_Zs2[ROWS * 2048];
__device__ __nv_bfloat16 g_Wqkv2[3 * D_MODEL * 2048];
__device__ __nv_bfloat16 g_Wo2[D_MODEL * 2048];
// attention per-head panels: [bh][t][64]
__device__ __nv_bfloat16 g_Qh[NBH * SEQ * DHEAD];
__device__ __nv_bfloat16 g_Ql[NBH * SEQ * DHEAD];
__device__ __nv_bfloat16 g_Kh[NBH * SEQ * DHEAD];
__device__ __nv_bfloat16 g_Kl[NBH * SEQ * DHEAD];
__device__ __nv_bfloat16 g_Vh[NBH * SEQ * DHEAD];
__device__ __nv_bfloat16 g_Vl[NBH * SEQ * DHEAD];

// ---------------------------------------------------------------------------
// helpers
// ---------------------------------------------------------------------------
__device__ __forceinline__ uint32_t smem_u32(const void* p) {
    uint32_t a;
    asm("{ .reg .u64 t; cvta.to.shared.u64 t, %1; cvt.u32.u64 %0, t; }" : "=r"(a) : "l"(p));
    return a;
}
__device__ __forceinline__ void cp_async16(uint32_t dst, const void* src) {
    asm volatile("cp.async.cg.shared.global [%0], [%1], 16;" :: "r"(dst), "l"(src) : "memory");
}
__device__ __forceinline__ void cp_commit() {
    asm volatile("cp.async.commit_group;" ::: "memory");
}
__device__ __forceinline__ void cp_wait0() {
    asm volatile("cp.async.wait_group 0;" ::: "memory");
}
__device__ __forceinline__ void cp_wait1() {
    asm volatile("cp.async.wait_group 1;" ::: "memory");
}
__device__ __forceinline__ uint32_t sw128(uint32_t off) { return off ^ ((off >> 3) & 0x70); }
__device__ __forceinline__ void ldsm4(uint32_t& r0, uint32_t& r1, uint32_t& r2, uint32_t& r3,
                                      uint32_t addr) {
    asm volatile("ldmatrix.sync.aligned.m8n8.x4.shared.b16 {%0,%1,%2,%3}, [%4];"
                 : "=r"(r0), "=r"(r1), "=r"(r2), "=r"(r3) : "r"(addr));
}
__device__ __forceinline__ void ldsm4t(uint32_t& r0, uint32_t& r1, uint32_t& r2, uint32_t& r3,
                                       uint32_t addr) {
    asm volatile("ldmatrix.sync.aligned.m8n8.x4.trans.shared.b16 {%0,%1,%2,%3}, [%4];"
                 : "=r"(r0), "=r"(r1), "=r"(r2), "=r"(r3) : "r"(addr));
}
__device__ __forceinline__ void mma16816(float* c, const uint32_t* a, const uint32_t* b) {
    asm volatile(
        "mma.sync.aligned.m16n8k16.row.col.f32.bf16.bf16.f32 "
        "{%0,%1,%2,%3}, {%4,%5,%6,%7}, {%8,%9}, {%0,%1,%2,%3};"
        : "+f"(c[0]), "+f"(c[1]), "+f"(c[2]), "+f"(c[3])
        : "r"(a[0]), "r"(a[1]), "r"(a[2]), "r"(a[3]), "r"(b[0]), "r"(b[1]));
}
__device__ __forceinline__ float ex2f(float x) {
    float y; asm("ex2.approx.ftz.f32 %0, %1;" : "=f"(y) : "f"(x)); return y;
}
__device__ __forceinline__ uint32_t packbf(float hi, float lo) {
    uint32_t r; asm("cvt.rn.bf16x2.f32 %0, %1, %2;" : "=r"(r) : "f"(hi), "f"(lo)); return r;
}
__device__ __forceinline__ float qsum(float v) {
    v += __shfl_xor_sync(0xffffffffu, v, 1);
    v += __shfl_xor_sync(0xffffffffu, v, 2);
    return v;
}
__device__ __forceinline__ float qmax(float v) {
    v = fmaxf(v, __shfl_xor_sync(0xffffffffu, v, 1));
    v = fmaxf(v, __shfl_xor_sync(0xffffffffu, v, 2));
    return v;
}
__device__ __forceinline__ void split2(float x, __nv_bfloat16& h, __nv_bfloat16& l) {
    h = __float2bfloat16_rn(x);
    l = __float2bfloat16_rn(x - __bfloat162float(h));
}

// ---------------------------------------------------------------------------
// conversions
// ---------------------------------------------------------------------------
__global__ void convX_kernel(const float* __restrict__ src)
{
    int i = blockIdx.x * blockDim.x + threadIdx.x;
    if (i >= ROWS * D_MODEL) return;
    int row = i >> 10, c = i & 1023;
    __nv_bfloat16 h, l;
    split2(src[i], h, l);
    size_t o = (size_t)row * 2048 + (c >> 5) * 64 + (c & 31);
    g_Xs2[o] = h; g_Xs2[o + 32] = l;
}

__global__ void convW_kernel(const float* __restrict__ Wq, const float* __restrict__ Wk,
                             const float* __restrict__ Wv, const float* __restrict__ Wo)
{
    int which = blockIdx.y;
    const float* src = (which == 0) ? Wq : (which == 1) ? Wk : (which == 2) ? Wv : Wo;
    __nv_bfloat16* dst = (which < 3) ? (g_Wqkv2 + (size_t)which * D_MODEL * 2048) : g_Wo2;
    int i = blockIdx.x * blockDim.x + threadIdx.x;
    if (i >= D_MODEL * D_MODEL) return;
    int row = i >> 10, c = i & 1023;
    __nv_bfloat16 h, l;
    split2(src[i], h, l);
    size_t o = (size_t)row * 2048 + (c >> 5) * 64 + (c & 31);
    dst[o] = h; dst[o + 32] = l;
}

// ---------------------------------------------------------------------------
// 2-slot HMMA GEMM (R11 form): CTA 128x128, 256 thr, 3 stages, single-sync
// pipelined mainloop, 2 CTA/SM.
// ---------------------------------------------------------------------------
#define BMg 128
#define BNg 128
#define NCH 32
#define STA (BMg * 128)        // 16384
#define STB (BNg * 128)        // 16384
#define STAGE (STA + STB)      // 32768
#define GSMEM (3 * STAGE)      // 98304

__global__ void __launch_bounds__(256, 2)
gemm2s_kernel(float* __restrict__ outp, int mode)
{
    extern __shared__ char smem[];
    const uint32_t sbase = smem_u32(smem);
    const int tid = threadIdx.x;
    const int wid = tid >> 5;
    const int lane = tid & 31;
    const int wm = wid >> 2;
    const int wn = wid & 3;
    const int m0 = blockIdx.y * BMg;
    const int n0 = blockIdx.x * BNg;

    const __nv_bfloat16* A = (mode == 0) ? g_Xs2 : g_Zs2;
    const __nv_bfloat16* B = (mode == 0) ? g_Wqkv2 : g_Wo2;
    const __nv_bfloat16* Abase = A + (size_t)m0 * 2048;
    const __nv_bfloat16* Bbase = B + (size_t)n0 * 2048;

    auto fill = [&](int stage, int chunk) {
        uint32_t base = sbase + stage * STAGE;
        #pragma unroll
        for (int i = 0; i < 8; i++) {
            int g = i * 256 + tid;
            if (g < 1024) {
                int row = g >> 3, gr = g & 7;
                cp_async16(base + sw128((uint32_t)(row * 128 + gr * 16)),
                           Abase + (size_t)row * 2048 + chunk * 64 + gr * 8);
            } else {
                int bi = g - 1024;
                int row = bi >> 3, gr = bi & 7;
                cp_async16(base + STA + sw128((uint32_t)(row * 128 + gr * 16)),
                           Bbase + (size_t)row * 2048 + chunk * 64 + gr * 8);
            }
        }
    };

    float acc[4][4][4] = {};

    fill(0, 0); cp_commit();
    fill(1, 1); cp_commit();
    cp_wait1(); __syncthreads();

    for (int c = 0; c < NCH; c++) {
        if (c + 2 < NCH) fill((c + 2) % 3, c + 2);
        cp_commit();

        uint32_t abase = sbase + (c % 3) * STAGE;
        uint32_t bbase = abase + STA;

        #pragma unroll
        for (int s = 0; s < 2; s++) {
            const int kb = s * 32;
            uint32_t af[4][4];
            #pragma unroll
            for (int mt = 0; mt < 4; mt++) {
                int row = wm * 64 + mt * 16 + (lane & 15);
                ldsm4(af[mt][0], af[mt][1], af[mt][2], af[mt][3],
                      abase + sw128((uint32_t)(row * 128 + kb + (lane >> 4) * 16)));
            }
            uint32_t bh[4][2];
            #pragma unroll
            for (int bt = 0; bt < 2; bt++) {
                int row = wn * 32 + bt * 16 + (lane & 7) + ((lane >> 4) & 1) * 8;
                int col = kb + (((lane >> 3) & 1) * 16);
                ldsm4(bh[2 * bt][0], bh[2 * bt][1], bh[2 * bt + 1][0], bh[2 * bt + 1][1],
                      bbase + sw128((uint32_t)(row * 128 + col)));
            }
            #pragma unroll
            for (int mt = 0; mt < 4; mt++)
                #pragma unroll
                for (int nt = 0; nt < 4; nt++)
                    mma16816(acc[mt][nt], af[mt], bh[nt]);
            uint32_t bl[4][2];
            #pragma unroll
            for (int bt = 0; bt < 2; bt++) {
                int row = wn * 32 + bt * 16 + (lane & 7) + ((lane >> 4) & 1) * 8;
                int col = 64 + kb + (((lane >> 3) & 1) * 16);
                ldsm4(bl[2 * bt][0], bl[2 * bt][1], bl[2 * bt + 1][0], bl[2 * bt + 1][1],
                      bbase + sw128((uint32_t)(row * 128 + col)));
            }
            #pragma unroll
            for (int mt = 0; mt < 4; mt++)
                #pragma unroll
                for (int nt = 0; nt < 4; nt++)
                    mma16816(acc[mt][nt], af[mt], bl[nt]);
            #pragma unroll
            for (int mt = 0; mt < 4; mt++) {
                int row = wm * 64 + mt * 16 + (lane & 15);
                ldsm4(af[mt][0], af[mt][1], af[mt][2], af[mt][3],
                      abase + sw128((uint32_t)(row * 128 + 64 + kb + (lane >> 4) * 16)));
            }
            #pragma unroll
            for (int mt = 0; mt < 4; mt++)
                #pragma unroll
                for (int nt = 0; nt < 4; nt++)
                    mma16816(acc[mt][nt], af[mt], bh[nt]);
        }

        cp_wait1();
        __syncthreads();
    }

    const int gid = lane >> 2;
    const int tid2 = lane & 3;
    if (mode == 1) {
        #pragma unroll
        for (int mt = 0; mt < 4; mt++) {
            int row0 = m0 + wm * 64 + mt * 16 + gid;
            #pragma unroll
            for (int nt = 0; nt < 4; nt++) {
                int ncol = n0 + wn * 32 + nt * 8 + tid2 * 2;
                *(float2*)(outp + (size_t)row0 * 1024 + ncol) =
                    make_float2(acc[mt][nt][0], acc[mt][nt][1]);
                *(float2*)(outp + (size_t)(row0 + 8) * 1024 + ncol) =
                    make_float2(acc[mt][nt][2], acc[mt][nt][3]);
            }
        }
        return;
    }
    #pragma unroll
    for (int mt = 0; mt < 4; mt++) {
        int row0 = m0 + wm * 64 + mt * 16 + gid;
        #pragma unroll
        for (int nt = 0; nt < 4; nt++) {
            int ncol = n0 + wn * 32 + nt * 8 + tid2 * 2;
            int which = ncol >> 10;
            int c = ncol & 1023;
            int h = c >> 6, d = c & 63;
            __nv_bfloat16* hiA = (which == 0) ? g_Qh : (which == 1) ? g_Kh : g_Vh;
            __nv_bfloat16* loA = (which == 0) ? g_Ql : (which == 1) ? g_Kl : g_Vl;
            float sc = (which == 0) ? QSCALE : 1.0f;
            #pragma unroll
            for (int rr = 0; rr < 2; rr++) {
                int row = row0 + rr * 8;
                int b = row >> 11, t = row & 2047;
                size_t base = ((size_t)(b * NHEADS + h) * SEQ + t) * 64 + d;
                float v0 = acc[mt][nt][2 * rr] * sc;
                float v1 = acc[mt][nt][2 * rr + 1] * sc;
                __nv_bfloat16 h0, l0, h1, l1;
                split2(v0, h0, l0); split2(v1, h1, l1);
                *(__nv_bfloat162*)(hiA + base) = __nv_bfloat162(h0, h1);
                *(__nv_bfloat162*)(loA + base) = __nv_bfloat162(l0, l1);
            }
        }
    }
}

// ---------------------------------------------------------------------------
// 2-slot HMMA flash attention + exclusive output mod
// R12: S-phase uses 4 independent accumulator chains per warp (a0/a1 for
// Qh*Kh depth-4; b0/b1 for Qh*Kl + Ql*Kh depth-8) merged with FADDs —
// doubles tensor-pipe ILP in the weakest phase.
// ---------------------------------------------------------------------------
#define AST 32768
#define ASMEM (3 * AST)          // 98304
#define NKV (SEQ / 64)           // 32

__global__ void __launch_bounds__(256, 2)
attn_mma_kernel()
{
    extern __shared__ char smem[];
    const uint32_t sb = smem_u32(smem);
    const int tid = threadIdx.x;
    const int wid = tid >> 5;       // 0..7
    const int lane = tid & 31;
    const int bh = blockIdx.x;
    const int q0 = blockIdx.y * 128;
    const int b_ = bh >> 4, h_ = bh & 15;

    const __nv_bfloat16* Qhs = g_Qh + ((size_t)bh * SEQ + q0) * 64;
    const __nv_bfloat16* Qls = g_Ql + ((size_t)bh * SEQ + q0) * 64;
    const __nv_bfloat16* Khs = g_Kh + (size_t)bh * SEQ * 64;
    const __nv_bfloat16* Kls = g_Kl + (size_t)bh * SEQ * 64;
    const __nv_bfloat16* Vhs = g_Vh + (size_t)bh * SEQ * 64;
    const __nv_bfloat16* Vls = g_Vl + (size_t)bh * SEQ * 64;

    // ---- stage Q through stage-2 smem, extract fragments to registers
    #pragma unroll
    for (int i = 0; i < 8; i++) {
        int g = i * 256 + tid;
        int panel = g >> 10, idx = g & 1023;
        int row = idx >> 3, gr = idx & 7;
        const __nv_bfloat16* src = (panel ? Qls : Qhs) + (size_t)row * 64 + gr * 8;
        cp_async16(sb + 2 * AST + panel * 16384 + sw128((uint32_t)(row * 128 + gr * 16)), src);
    }
    cp_commit(); cp_wait0(); __syncthreads();

    uint32_t qh[4][4], ql[4][4];
    const int arow = wid * 16 + (lane & 15);
    #pragma unroll
    for (int s = 0; s < 4; s++) {
        const int cb = s * 32 + (lane >> 4) * 16;
        ldsm4(qh[s][0], qh[s][1], qh[s][2], qh[s][3],
              sb + 2 * AST + sw128((uint32_t)(arow * 128 + cb)));
        ldsm4(ql[s][0], ql[s][1], ql[s][2], ql[s][3],
              sb + 2 * AST + 16384 + sw128((uint32_t)(arow * 128 + cb)));
    }
    __syncthreads();

    auto fillKV = [&](int stage, int kt) {
        uint32_t base = sb + stage * AST;
        int t0 = kt * 64;
        #pragma unroll
        for (int i = 0; i < 8; i++) {
            int g = i * 256 + tid;
            int seg = g >> 9, idx = g & 511;
            int row = idx >> 3, gr = idx & 7;
            const __nv_bfloat16* src =
                (seg == 0) ? Khs : (seg == 1) ? Kls : (seg == 2) ? Vhs : Vls;
            cp_async16(base + seg * 8192 + sw128((uint32_t)(row * 128 + gr * 16)),
                       src + (size_t)(t0 + row) * 64 + gr * 8);
        }
    };

    fillKV(0, 0); cp_commit();
    fillKV(1, 1); cp_commit();
    cp_wait1(); __syncthreads();     // stage 0 ready; stage-1 fill in flight

    float accO[8][4] = {};
    float accS[8][4];
    float m0 = -CUDART_INF_F, m1 = -CUDART_INF_F;
    float l0 = 0.0f, l1 = 0.0f;

    for (int kt = 0; kt < NKV; kt++) {
        if (kt + 2 < NKV) fillKV((kt + 2) % 3, kt + 2);
        cp_commit();

        const uint32_t kb = sb + (kt % 3) * AST;
        const uint32_t klb = kb + 8192;

        // ---- S = Qh*Kh + Qh*Kl + Ql*Kh, 4 accumulation chains per warp
        #pragma unroll
        for (int nb = 0; nb < 4; nb++) {
            int row = nb * 16 + (lane & 7) + ((lane >> 4) & 1) * 8;
            float a0[4] = {}, a1[4] = {};   // Qh*Kh chains (depth 4)
            float b0[4] = {}, b1[4] = {};   // Qh*Kl + Ql*Kh chains (depth 8)
            #pragma unroll
            for (int s = 0; s < 4; s++) {
                int off = s * 32 + ((lane >> 3) & 1) * 16;
                uint32_t bhf[4], blf[4];
                ldsm4(bhf[0], bhf[1], bhf[2], bhf[3], kb + sw128((uint32_t)(row * 128 + off)));
                ldsm4(blf[0], blf[1], blf[2], blf[3], klb + sw128((uint32_t)(row * 128 + off)));
                mma16816(a0, qh[s], &bhf[0]);
                mma16816(a1, qh[s], &bhf[2]);
                mma16816(b0, qh[s], &blf[0]);
                mma16816(b1, qh[s], &blf[2]);
                mma16816(b0, ql[s], &bhf[0]);
                mma16816(b1, ql[s], &bhf[2]);
            }
            #pragma unroll
            for (int r = 0; r < 4; r++) {
                accS[2 * nb][r]     = a0[r] + b0[r];
                accS[2 * nb + 1][r] = a1[r] + b1[r];
            }
        }

        // ---- online softmax (base-2)
        float mx0 = -CUDART_INF_F, mx1 = -CUDART_INF_F;
        #pragma unroll
        for (int nt = 0; nt < 8; nt++) {
            mx0 = fmaxf(mx0, fmaxf(accS[nt][0], accS[nt][1]));
            mx1 = fmaxf(mx1, fmaxf(accS[nt][2], accS[nt][3]));
        }
        mx0 = qmax(mx0); mx1 = qmax(mx1);
        float m0n = fmaxf(m0, mx0), m1n = fmaxf(m1, mx1);
        float c0 = ex2f(m0 - m0n), c1 = ex2f(m1 - m1n);
        m0 = m0n; m1 = m1n;
        float s0 = 0.0f, s1 = 0.0f;
        #pragma unroll
        for (int nt = 0; nt < 8; nt++) {
            accS[nt][0] = ex2f(accS[nt][0] - m0);
            accS[nt][1] = ex2f(accS[nt][1] - m0);
            accS[nt][2] = ex2f(accS[nt][2] - m1);
            accS[nt][3] = ex2f(accS[nt][3] - m1);
            s0 += accS[nt][0] + accS[nt][1];
            s1 += accS[nt][2] + accS[nt][3];
            accO[nt][0] *= c0; accO[nt][1] *= c0;
            accO[nt][2] *= c1; accO[nt][3] *= c1;
        }
        l0 = l0 * c0 + qsum(s0);
        l1 = l1 * c1 + qsum(s1);

        // ---- PV: Ph*Vh + Ph*Vl + Pl*Vh
        const uint32_t vhb = kb + 16384, vlb = kb + 24576;
        #pragma unroll
        for (int j = 0; j < 4; j++) {
            uint32_t aPh[4], aPl[4];
            #pragma unroll
            for (int half = 0; half < 2; half++) {
                const float* a = accS[2 * j + half];
                uint32_t ph0 = packbf(a[1], a[0]);
                uint32_t ph1 = packbf(a[3], a[2]);
                float pl0e = a[0] - __uint_as_float(ph0 << 16);
                float pl0o = a[1] - __uint_as_float(ph0 & 0xffff0000u);
                float pl1e = a[2] - __uint_as_float(ph1 << 16);
                float pl1o = a[3] - __uint_as_float(ph1 & 0xffff0000u);
                aPh[2 * half]     = ph0;
                aPh[2 * half + 1] = ph1;
                aPl[2 * half]     = packbf(pl0o, pl0e);
                aPl[2 * half + 1] = packbf(pl1o, pl1e);
            }
            int vrow = j * 16 + ((lane >> 3) & 1) * 8 + (lane & 7);
            #pragma unroll
            for (int jc = 0; jc < 4; jc++) {
                int colb = (jc * 16 + ((lane >> 4) & 1) * 8) * 2;
                uint32_t vh[4], vl[4];
                ldsm4t(vh[0], vh[1], vh[2], vh[3],
                       vhb + sw128((uint32_t)(vrow * 128 + colb)));
                ldsm4t(vl[0], vl[1], vl[2], vl[3],
                       vlb + sw128((uint32_t)(vrow * 128 + colb)));
                mma16816(accO[2 * jc],     aPh, &vh[0]);
                mma16816(accO[2 * jc + 1], aPh, &vh[2]);
                mma16816(accO[2 * jc],     aPh, &vl[0]);
                mma16816(accO[2 * jc + 1], aPh, &vl[2]);
                mma16816(accO[2 * jc],     aPl, &vh[0]);
                mma16816(accO[2 * jc + 1], aPl, &vh[2]);
            }
        }

        cp_wait1();
        __syncthreads();
    }

    // ---- epilogue: normalize + exclusive output mod, write Z in 2-slot layout
    const float inv0 = 1.0f / l0, inv1 = 1.0f / l1;
    const int t_base = q0 + wid * 16 + (lane >> 2);
    const int dbase = (lane & 3) * 2;

    #pragma unroll
    for (int rs = 0; rs < 2; rs++) {
        int t = t_base + rs * 8;
        float inv = rs ? inv1 : inv0;
        float vv[8][2];
        float vsq = 0.0f, ydv = 0.0f, ysq = 0.0f;
        #pragma unroll
        for (int nt = 0; nt < 8; nt++) {
            size_t vb = ((size_t)bh * SEQ + t) * 64 + dbase + nt * 8;
            __nv_bfloat162 vh2 = *(const __nv_bfloat162*)(g_Vh + vb);
            __nv_bfloat162 vl2 = *(const __nv_bfloat162*)(g_Vl + vb);
            float vx = __bfloat162float(vh2.x) + __bfloat162float(vl2.x);
            float vy = __bfloat162float(vh2.y) + __bfloat162float(vl2.y);
            vv[nt][0] = vx; vv[nt][1] = vy;
            float y0 = accO[nt][2 * rs] * inv;
            float y1 = accO[nt][2 * rs + 1] * inv;
            accO[nt][2 * rs] = y0; accO[nt][2 * rs + 1] = y1;
            vsq = fmaf(vx, vx, fmaf(vy, vy, vsq));
            ydv = fmaf(y0, vx, fmaf(y1, vy, ydv));
            ysq = fmaf(y0, y0, fmaf(y1, y1, ysq));
        }
        vsq = qsum(vsq); ydv = qsum(ydv); ysq = qsum(ysq);
        float scale = (vsq > 0.0f) ? (ydv / fmaxf(vsq, FLT_MIN)) : 0.0f;
        float zsq = 0.0f;
        float zz[8][2];
        #pragma unroll
        for (int nt = 0; nt < 8; nt++) {
            float z0 = accO[nt][2 * rs] - scale * vv[nt][0];
            float z1 = accO[nt][2 * rs + 1] - scale * vv[nt][1];
            zz[nt][0] = z0; zz[nt][1] = z1;
            zsq = fmaf(z0, z0, fmaf(z1, z1, zsq));
        }
        zsq = qsum(zsq);
        float ref_norm = fmaxf(sqrtf(ysq), sqrtf(vsq));
        float tol = FLT_EPSILON * 64.0f * ref_norm;
        bool zero_out = (vsq > 0.0f) && (sqrtf(zsq) <= tol);
        size_t zrow = (size_t)(b_ * SEQ + t) * 2048;
        #pragma unroll
        for (int nt = 0; nt < 8; nt++) {
            float z0 = zero_out ? 0.0f : zz[nt][0];
            float z1 = zero_out ? 0.0f : zz[nt][1];
            int c = h_ * 64 + dbase + nt * 8;
            size_t o = zrow + (c >> 5) * 64 + (c & 31);
            __nv_bfloat16 h0, l0b, h1, l1b;
            split2(z0, h0, l0b); split2(z1, h1, l1b);
            *(__nv_bfloat162*)(g_Zs2 + o) = __nv_bfloat162(h0, h1);
            *(__nv_bfloat162*)(g_Zs2 + o + 32) = __nv_bfloat162(l0b, l1b);
        }
    }
}

// ---------------------------------------------------------------------------
extern "C" void kernel_launch(void* const* d_in, const int* in_sizes, int n_in,
                              void* d_out, int out_size)
{
    const float* x  = (const float*)d_in[0];
    const float* Wq = (const float*)d_in[1];
    const float* Wk = (const float*)d_in[2];
    const float* Wv = (const float*)d_in[3];
    const float* Wo = (const float*)d_in[4];
    float* out = (float*)d_out;

    cudaFuncSetAttribute(gemm2s_kernel, cudaFuncAttributeMaxDynamicSharedMemorySize, GSMEM);
    cudaFuncSetAttribute(attn_mma_kernel, cudaFuncAttributeMaxDynamicSharedMemorySize, ASMEM);

    convX_kernel<<<(ROWS * D_MODEL + 255) / 256, 256>>>(x);
    dim3 gw((D_MODEL * D_MODEL + 255) / 256, 4);
    convW_kernel<<<gw, 256>>>(Wq, Wk, Wv, Wo);

    dim3 gqkv(3 * D_MODEL / BNg, ROWS / BMg);   // (24, 32)
    gemm2s_kernel<<<gqkv, 256, GSMEM>>>(nullptr, 0);

    dim3 gattn(NBH, SEQ / 128);                 // (32, 16)
    attn_mma_kernel<<<gattn, 256, ASMEM>>>();

    dim3 gout(D_MODEL / BNg, ROWS / BMg);       // (8, 32)
    gemm2s_kernel<<<gout, 256, GSMEM>>>(out, 1);
}

// round 13
// speedup vs baseline: 1.0210x; 1.0210x over previous
#include <cuda_runtime.h>
#include <cuda_bf16.h>
#include <math_constants.h>
#include <cfloat>
#include <cstdint>

#define D_MODEL 1024
#define NHEADS  16
#define DHEAD   64
#define BATCH   2
#define SEQ     2048
#define ROWS    (BATCH * SEQ)   // 4096
#define NBH     (BATCH * NHEADS)
#define QSCALE  0.18033688011112042f   // 0.125 * log2(e)

// 2-slot operands. GEMM A/B layout: [row][chunk32][hi 32 | lo 32], row stride 2048.
__device__ __nv_bfloat16 g_Xs2[ROWS * 2048];
__device__ __nv_bfloat16 g_Zs2[ROWS * 2048];
__device__ __nv_bfloat16 g_Wqkv2[3 * D_MODEL * 2048];
__device__ __nv_bfloat16 g_Wo2[D_MODEL * 2048];
// attention per-head panels: [bh][t][64]
__device__ __nv_bfloat16 g_Qh[NBH * SEQ * DHEAD];
__device__ __nv_bfloat16 g_Ql[NBH * SEQ * DHEAD];
__device__ __nv_bfloat16 g_Kh[NBH * SEQ * DHEAD];
__device__ __nv_bfloat16 g_Kl[NBH * SEQ * DHEAD];
__device__ __nv_bfloat16 g_Vh[NBH * SEQ * DHEAD];
__device__ __nv_bfloat16 g_Vl[NBH * SEQ * DHEAD];

// ---------------------------------------------------------------------------
// helpers
// ---------------------------------------------------------------------------
__device__ __forceinline__ uint32_t smem_u32(const void* p) {
    uint32_t a;
    asm("{ .reg .u64 t; cvta.to.shared.u64 t, %1; cvt.u32.u64 %0, t; }" : "=r"(a) : "l"(p));
    return a;
}
__device__ __forceinline__ void cp_async16(uint32_t dst, const void* src) {
    asm volatile("cp.async.cg.shared.global [%0], [%1], 16;" :: "r"(dst), "l"(src) : "memory");
}
__device__ __forceinline__ void cp_commit() {
    asm volatile("cp.async.commit_group;" ::: "memory");
}
__device__ __forceinline__ void cp_wait0() {
    asm volatile("cp.async.wait_group 0;" ::: "memory");
}
__device__ __forceinline__ void cp_wait1() {
    asm volatile("cp.async.wait_group 1;" ::: "memory");
}
__device__ __forceinline__ uint32_t sw128(uint32_t off) { return off ^ ((off >> 3) & 0x70); }
__device__ __forceinline__ void ldsm4(uint32_t& r0, uint32_t& r1, uint32_t& r2, uint32_t& r3,
                                      uint32_t addr) {
    asm volatile("ldmatrix.sync.aligned.m8n8.x4.shared.b16 {%0,%1,%2,%3}, [%4];"
                 : "=r"(r0), "=r"(r1), "=r"(r2), "=r"(r3) : "r"(addr));
}
__device__ __forceinline__ void ldsm4t(uint32_t& r0, uint32_t& r1, uint32_t& r2, uint32_t& r3,
                                       uint32_t addr) {
    asm volatile("ldmatrix.sync.aligned.m8n8.x4.trans.shared.b16 {%0,%1,%2,%3}, [%4];"
                 : "=r"(r0), "=r"(r1), "=r"(r2), "=r"(r3) : "r"(addr));
}
__device__ __forceinline__ void mma16816(float* c, const uint32_t* a, const uint32_t* b) {
    asm volatile(
        "mma.sync.aligned.m16n8k16.row.col.f32.bf16.bf16.f32 "
        "{%0,%1,%2,%3}, {%4,%5,%6,%7}, {%8,%9}, {%0,%1,%2,%3};"
        : "+f"(c[0]), "+f"(c[1]), "+f"(c[2]), "+f"(c[3])
        : "r"(a[0]), "r"(a[1]), "r"(a[2]), "r"(a[3]), "r"(b[0]), "r"(b[1]));
}
__device__ __forceinline__ float ex2f(float x) {
    float y; asm("ex2.approx.ftz.f32 %0, %1;" : "=f"(y) : "f"(x)); return y;
}
__device__ __forceinline__ uint32_t packbf(float hi, float lo) {
    uint32_t r; asm("cvt.rn.bf16x2.f32 %0, %1, %2;" : "=r"(r) : "f"(hi), "f"(lo)); return r;
}
__device__ __forceinline__ float qsum(float v) {
    v += __shfl_xor_sync(0xffffffffu, v, 1);
    v += __shfl_xor_sync(0xffffffffu, v, 2);
    return v;
}
__device__ __forceinline__ float qmax(float v) {
    v = fmaxf(v, __shfl_xor_sync(0xffffffffu, v, 1));
    v = fmaxf(v, __shfl_xor_sync(0xffffffffu, v, 2));
    return v;
}
__device__ __forceinline__ void split2(float x, __nv_bfloat16& h, __nv_bfloat16& l) {
    h = __float2bfloat16_rn(x);
    l = __float2bfloat16_rn(x - __bfloat162float(h));
}

// ---------------------------------------------------------------------------
// merged conversion: x (4M elems) + 4 weights (4M elems) in one launch
// region 0: x -> g_Xs2; regions 1-4: Wq/Wk/Wv -> g_Wqkv2, Wo -> g_Wo2
// ---------------------------------------------------------------------------
__global__ void conv_all_kernel(const float* __restrict__ x,
                                const float* __restrict__ Wq,
                                const float* __restrict__ Wk,
                                const float* __restrict__ Wv,
                                const float* __restrict__ Wo)
{
    int gi = blockIdx.x * blockDim.x + threadIdx.x;
    const int NX = ROWS * D_MODEL;          // 4M
    const int NW = D_MODEL * D_MODEL;       // 1M
    const float* src;
    __nv_bfloat16* dst;
    int i;
    if (gi < NX) {
        src = x; dst = g_Xs2; i = gi;
    } else {
        int wi = gi - NX;
        int which = wi >> 20;               // NW = 1<<20
        i = wi & (NW - 1);
        src = (which == 0) ? Wq : (which == 1) ? Wk : (which == 2) ? Wv : Wo;
        dst = (which < 3) ? (g_Wqkv2 + (size_t)which * D_MODEL * 2048) : g_Wo2;
    }
    int row = i >> 10, c = i & 1023;
    __nv_bfloat16 h, l;
    split2(src[i], h, l);
    size_t o = (size_t)row * 2048 + (c >> 5) * 64 + (c & 31);
    dst[o] = h; dst[o + 32] = l;
}

// ---------------------------------------------------------------------------
// 2-slot HMMA GEMM (R11 form): CTA 128x128, 256 thr, 3 stages, single-sync
// pipelined mainloop, 2 CTA/SM.
// ---------------------------------------------------------------------------
#define BMg 128
#define BNg 128
#define NCH 32
#define STA (BMg * 128)        // 16384
#define STB (BNg * 128)        // 16384
#define STAGE (STA + STB)      // 32768
#define GSMEM (3 * STAGE)      // 98304

__global__ void __launch_bounds__(256, 2)
gemm2s_kernel(float* __restrict__ outp, int mode)
{
    extern __shared__ char smem[];
    const uint32_t sbase = smem_u32(smem);
    const int tid = threadIdx.x;
    const int wid = tid >> 5;
    const int lane = tid & 31;
    const int wm = wid >> 2;
    const int wn = wid & 3;
    const int m0 = blockIdx.y * BMg;
    const int n0 = blockIdx.x * BNg;

    const __nv_bfloat16* A = (mode == 0) ? g_Xs2 : g_Zs2;
    const __nv_bfloat16* B = (mode == 0) ? g_Wqkv2 : g_Wo2;
    const __nv_bfloat16* Abase = A + (size_t)m0 * 2048;
    const __nv_bfloat16* Bbase = B + (size_t)n0 * 2048;

    auto fill = [&](int stage, int chunk) {
        uint32_t base = sbase + stage * STAGE;
        #pragma unroll
        for (int i = 0; i < 8; i++) {
            int g = i * 256 + tid;
            if (g < 1024) {
                int row = g >> 3, gr = g & 7;
                cp_async16(base + sw128((uint32_t)(row * 128 + gr * 16)),
                           Abase + (size_t)row * 2048 + chunk * 64 + gr * 8);
            } else {
                int bi = g - 1024;
                int row = bi >> 3, gr = bi & 7;
                cp_async16(base + STA + sw128((uint32_t)(row * 128 + gr * 16)),
                           Bbase + (size_t)row * 2048 + chunk * 64 + gr * 8);
            }
        }
    };

    float acc[4][4][4] = {};

    fill(0, 0); cp_commit();
    fill(1, 1); cp_commit();
    cp_wait1(); __syncthreads();

    for (int c = 0; c < NCH; c++) {
        if (c + 2 < NCH) fill((c + 2) % 3, c + 2);
        cp_commit();

        uint32_t abase = sbase + (c % 3) * STAGE;
        uint32_t bbase = abase + STA;

        #pragma unroll
        for (int s = 0; s < 2; s++) {
            const int kb = s * 32;
            uint32_t af[4][4];
            #pragma unroll
            for (int mt = 0; mt < 4; mt++) {
                int row = wm * 64 + mt * 16 + (lane & 15);
                ldsm4(af[mt][0], af[mt][1], af[mt][2], af[mt][3],
                      abase + sw128((uint32_t)(row * 128 + kb + (lane >> 4) * 16)));
            }
            uint32_t bh[4][2];
            #pragma unroll
            for (int bt = 0; bt < 2; bt++) {
                int row = wn * 32 + bt * 16 + (lane & 7) + ((lane >> 4) & 1) * 8;
                int col = kb + (((lane >> 3) & 1) * 16);
                ldsm4(bh[2 * bt][0], bh[2 * bt][1], bh[2 * bt + 1][0], bh[2 * bt + 1][1],
                      bbase + sw128((uint32_t)(row * 128 + col)));
            }
            #pragma unroll
            for (int mt = 0; mt < 4; mt++)
                #pragma unroll
                for (int nt = 0; nt < 4; nt++)
                    mma16816(acc[mt][nt], af[mt], bh[nt]);
            uint32_t bl[4][2];
            #pragma unroll
            for (int bt = 0; bt < 2; bt++) {
                int row = wn * 32 + bt * 16 + (lane & 7) + ((lane >> 4) & 1) * 8;
                int col = 64 + kb + (((lane >> 3) & 1) * 16);
                ldsm4(bl[2 * bt][0], bl[2 * bt][1], bl[2 * bt + 1][0], bl[2 * bt + 1][1],
                      bbase + sw128((uint32_t)(row * 128 + col)));
            }
            #pragma unroll
            for (int mt = 0; mt < 4; mt++)
                #pragma unroll
                for (int nt = 0; nt < 4; nt++)
                    mma16816(acc[mt][nt], af[mt], bl[nt]);
            #pragma unroll
            for (int mt = 0; mt < 4; mt++) {
                int row = wm * 64 + mt * 16 + (lane & 15);
                ldsm4(af[mt][0], af[mt][1], af[mt][2], af[mt][3],
                      abase + sw128((uint32_t)(row * 128 + 64 + kb + (lane >> 4) * 16)));
            }
            #pragma unroll
            for (int mt = 0; mt < 4; mt++)
                #pragma unroll
                for (int nt = 0; nt < 4; nt++)
                    mma16816(acc[mt][nt], af[mt], bh[nt]);
        }

        cp_wait1();
        __syncthreads();
    }

    const int gid = lane >> 2;
    const int tid2 = lane & 3;
    if (mode == 1) {
        #pragma unroll
        for (int mt = 0; mt < 4; mt++) {
            int row0 = m0 + wm * 64 + mt * 16 + gid;
            #pragma unroll
            for (int nt = 0; nt < 4; nt++) {
                int ncol = n0 + wn * 32 + nt * 8 + tid2 * 2;
                *(float2*)(outp + (size_t)row0 * 1024 + ncol) =
                    make_float2(acc[mt][nt][0], acc[mt][nt][1]);
                *(float2*)(outp + (size_t)(row0 + 8) * 1024 + ncol) =
                    make_float2(acc[mt][nt][2], acc[mt][nt][3]);
            }
        }
        return;
    }
    #pragma unroll
    for (int mt = 0; mt < 4; mt++) {
        int row0 = m0 + wm * 64 + mt * 16 + gid;
        #pragma unroll
        for (int nt = 0; nt < 4; nt++) {
            int ncol = n0 + wn * 32 + nt * 8 + tid2 * 2;
            int which = ncol >> 10;
            int c = ncol & 1023;
            int h = c >> 6, d = c & 63;
            __nv_bfloat16* hiA = (which == 0) ? g_Qh : (which == 1) ? g_Kh : g_Vh;
            __nv_bfloat16* loA = (which == 0) ? g_Ql : (which == 1) ? g_Kl : g_Vl;
            float sc = (which == 0) ? QSCALE : 1.0f;
            #pragma unroll
            for (int rr = 0; rr < 2; rr++) {
                int row = row0 + rr * 8;
                int b = row >> 11, t = row & 2047;
                size_t base = ((size_t)(b * NHEADS + h) * SEQ + t) * 64 + d;
                float v0 = acc[mt][nt][2 * rr] * sc;
                float v1 = acc[mt][nt][2 * rr + 1] * sc;
                __nv_bfloat16 h0, l0, h1, l1;
                split2(v0, h0, l0); split2(v1, h1, l1);
                *(__nv_bfloat162*)(hiA + base) = __nv_bfloat162(h0, h1);
                *(__nv_bfloat162*)(loA + base) = __nv_bfloat162(l0, l1);
            }
        }
    }
}

// ---------------------------------------------------------------------------
// 2-slot HMMA flash attention + exclusive output mod (R11 form — best measured)
// CTA: 128 q rows, 256 threads, 3 KV stages, Q in registers, one barrier/tile.
// ---------------------------------------------------------------------------
#define AST 32768
#define ASMEM (3 * AST)          // 98304
#define NKV (SEQ / 64)           // 32

__global__ void __launch_bounds__(256, 2)
attn_mma_kernel()
{
    extern __shared__ char smem[];
    const uint32_t sb = smem_u32(smem);
    const int tid = threadIdx.x;
    const int wid = tid >> 5;       // 0..7
    const int lane = tid & 31;
    const int bh = blockIdx.x;
    const int q0 = blockIdx.y * 128;
    const int b_ = bh >> 4, h_ = bh & 15;

    const __nv_bfloat16* Qhs = g_Qh + ((size_t)bh * SEQ + q0) * 64;
    const __nv_bfloat16* Qls = g_Ql + ((size_t)bh * SEQ + q0) * 64;
    const __nv_bfloat16* Khs = g_Kh + (size_t)bh * SEQ * 64;
    const __nv_bfloat16* Kls = g_Kl + (size_t)bh * SEQ * 64;
    const __nv_bfloat16* Vhs = g_Vh + (size_t)bh * SEQ * 64;
    const __nv_bfloat16* Vls = g_Vl + (size_t)bh * SEQ * 64;

    // ---- stage Q through stage-2 smem, extract fragments to registers
    #pragma unroll
    for (int i = 0; i < 8; i++) {
        int g = i * 256 + tid;
        int panel = g >> 10, idx = g & 1023;
        int row = idx >> 3, gr = idx & 7;
        const __nv_bfloat16* src = (panel ? Qls : Qhs) + (size_t)row * 64 + gr * 8;
        cp_async16(sb + 2 * AST + panel * 16384 + sw128((uint32_t)(row * 128 + gr * 16)), src);
    }
    cp_commit(); cp_wait0(); __syncthreads();

    uint32_t qh[4][4], ql[4][4];
    const int arow = wid * 16 + (lane & 15);
    #pragma unroll
    for (int s = 0; s < 4; s++) {
        const int cb = s * 32 + (lane >> 4) * 16;
        ldsm4(qh[s][0], qh[s][1], qh[s][2], qh[s][3],
              sb + 2 * AST + sw128((uint32_t)(arow * 128 + cb)));
        ldsm4(ql[s][0], ql[s][1], ql[s][2], ql[s][3],
              sb + 2 * AST + 16384 + sw128((uint32_t)(arow * 128 + cb)));
    }
    __syncthreads();

    auto fillKV = [&](int stage, int kt) {
        uint32_t base = sb + stage * AST;
        int t0 = kt * 64;
        #pragma unroll
        for (int i = 0; i < 8; i++) {
            int g = i * 256 + tid;
            int seg = g >> 9, idx = g & 511;
            int row = idx >> 3, gr = idx & 7;
            const __nv_bfloat16* src =
                (seg == 0) ? Khs : (seg == 1) ? Kls : (seg == 2) ? Vhs : Vls;
            cp_async16(base + seg * 8192 + sw128((uint32_t)(row * 128 + gr * 16)),
                       src + (size_t)(t0 + row) * 64 + gr * 8);
        }
    };

    fillKV(0, 0); cp_commit();
    fillKV(1, 1); cp_commit();
    cp_wait1(); __syncthreads();     // stage 0 ready; stage-1 fill in flight

    float accO[8][4] = {};
    float accS[8][4];
    float m0 = -CUDART_INF_F, m1 = -CUDART_INF_F;
    float l0 = 0.0f, l1 = 0.0f;

    for (int kt = 0; kt < NKV; kt++) {
        if (kt + 2 < NKV) fillKV((kt + 2) % 3, kt + 2);
        cp_commit();

        const uint32_t kb = sb + (kt % 3) * AST;
        const uint32_t klb = kb + 8192;

        // ---- S = Qh*Kh + Qh*Kl + Ql*Kh (Q from registers)
        #pragma unroll
        for (int nb = 0; nb < 4; nb++) {
            int row = nb * 16 + (lane & 7) + ((lane >> 4) & 1) * 8;
            float a0[4] = {}, a1[4] = {};
            #pragma unroll
            for (int s = 0; s < 4; s++) {
                int off = s * 32 + ((lane >> 3) & 1) * 16;
                uint32_t bhf[4], blf[4];
                ldsm4(bhf[0], bhf[1], bhf[2], bhf[3], kb + sw128((uint32_t)(row * 128 + off)));
                ldsm4(blf[0], blf[1], blf[2], blf[3], klb + sw128((uint32_t)(row * 128 + off)));
                mma16816(a0, qh[s], &bhf[0]);
                mma16816(a1, qh[s], &bhf[2]);
                mma16816(a0, qh[s], &blf[0]);
                mma16816(a1, qh[s], &blf[2]);
                mma16816(a0, ql[s], &bhf[0]);
                mma16816(a1, ql[s], &bhf[2]);
            }
            #pragma unroll
            for (int r = 0; r < 4; r++) { accS[2 * nb][r] = a0[r]; accS[2 * nb + 1][r] = a1[r]; }
        }

        // ---- online softmax (base-2)
        float mx0 = -CUDART_INF_F, mx1 = -CUDART_INF_F;
        #pragma unroll
        for (int nt = 0; nt < 8; nt++) {
            mx0 = fmaxf(mx0, fmaxf(accS[nt][0], accS[nt][1]));
            mx1 = fmaxf(mx1, fmaxf(accS[nt][2], accS[nt][3]));
        }
        mx0 = qmax(mx0); mx1 = qmax(mx1);
        float m0n = fmaxf(m0, mx0), m1n = fmaxf(m1, mx1);
        float c0 = ex2f(m0 - m0n), c1 = ex2f(m1 - m1n);
        m0 = m0n; m1 = m1n;
        float s0 = 0.0f, s1 = 0.0f;
        #pragma unroll
        for (int nt = 0; nt < 8; nt++) {
            accS[nt][0] = ex2f(accS[nt][0] - m0);
            accS[nt][1] = ex2f(accS[nt][1] - m0);
            accS[nt][2] = ex2f(accS[nt][2] - m1);
            accS[nt][3] = ex2f(accS[nt][3] - m1);
            s0 += accS[nt][0] + accS[nt][1];
            s1 += accS[nt][2] + accS[nt][3];
            accO[nt][0] *= c0; accO[nt][1] *= c0;
            accO[nt][2] *= c1; accO[nt][3] *= c1;
        }
        l0 = l0 * c0 + qsum(s0);
        l1 = l1 * c1 + qsum(s1);

        // ---- PV: Ph*Vh + Ph*Vl + Pl*Vh
        const uint32_t vhb = kb + 16384, vlb = kb + 24576;
        #pragma unroll
        for (int j = 0; j < 4; j++) {
            uint32_t aPh[4], aPl[4];
            #pragma unroll
            for (int half = 0; half < 2; half++) {
                const float* a = accS[2 * j + half];
                uint32_t ph0 = packbf(a[1], a[0]);
                uint32_t ph1 = packbf(a[3], a[2]);
                float pl0e = a[0] - __uint_as_float(ph0 << 16);
                float pl0o = a[1] - __uint_as_float(ph0 & 0xffff0000u);
                float pl1e = a[2] - __uint_as_float(ph1 << 16);
                float pl1o = a[3] - __uint_as_float(ph1 & 0xffff0000u);
                aPh[2 * half]     = ph0;
                aPh[2 * half + 1] = ph1;
                aPl[2 * half]     = packbf(pl0o, pl0e);
                aPl[2 * half + 1] = packbf(pl1o, pl1e);
            }
            int vrow = j * 16 + ((lane >> 3) & 1) * 8 + (lane & 7);
            #pragma unroll
            for (int jc = 0; jc < 4; jc++) {
                int colb = (jc * 16 + ((lane >> 4) & 1) * 8) * 2;
                uint32_t vh[4], vl[4];
                ldsm4t(vh[0], vh[1], vh[2], vh[3],
                       vhb + sw128((uint32_t)(vrow * 128 + colb)));
                ldsm4t(vl[0], vl[1], vl[2], vl[3],
                       vlb + sw128((uint32_t)(vrow * 128 + colb)));
                mma16816(accO[2 * jc],     aPh, &vh[0]);
                mma16816(accO[2 * jc + 1], aPh, &vh[2]);
                mma16816(accO[2 * jc],     aPh, &vl[0]);
                mma16816(accO[2 * jc + 1], aPh, &vl[2]);
                mma16816(accO[2 * jc],     aPl, &vh[0]);
                mma16816(accO[2 * jc + 1], aPl, &vh[2]);
            }
        }

        cp_wait1();
        __syncthreads();
    }

    // ---- epilogue: normalize + exclusive output mod, write Z in 2-slot layout
    const float inv0 = 1.0f / l0, inv1 = 1.0f / l1;
    const int t_base = q0 + wid * 16 + (lane >> 2);
    const int dbase = (lane & 3) * 2;

    #pragma unroll
    for (int rs = 0; rs < 2; rs++) {
        int t = t_base + rs * 8;
        float inv = rs ? inv1 : inv0;
        float vv[8][2];
        float vsq = 0.0f, ydv = 0.0f, ysq = 0.0f;
        #pragma unroll
        for (int nt = 0; nt < 8; nt++) {
            size_t vb = ((size_t)bh * SEQ + t) * 64 + dbase + nt * 8;
            __nv_bfloat162 vh2 = *(const __nv_bfloat162*)(g_Vh + vb);
            __nv_bfloat162 vl2 = *(const __nv_bfloat162*)(g_Vl + vb);
            float vx = __bfloat162float(vh2.x) + __bfloat162float(vl2.x);
            float vy = __bfloat162float(vh2.y) + __bfloat162float(vl2.y);
            vv[nt][0] = vx; vv[nt][1] = vy;
            float y0 = accO[nt][2 * rs] * inv;
            float y1 = accO[nt][2 * rs + 1] * inv;
            accO[nt][2 * rs] = y0; accO[nt][2 * rs + 1] = y1;
            vsq = fmaf(vx, vx, fmaf(vy, vy, vsq));
            ydv = fmaf(y0, vx, fmaf(y1, vy, ydv));
            ysq = fmaf(y0, y0, fmaf(y1, y1, ysq));
        }
        vsq = qsum(vsq); ydv = qsum(ydv); ysq = qsum(ysq);
        float scale = (vsq > 0.0f) ? (ydv / fmaxf(vsq, FLT_MIN)) : 0.0f;
        float zsq = 0.0f;
        float zz[8][2];
        #pragma unroll
        for (int nt = 0; nt < 8; nt++) {
            float z0 = accO[nt][2 * rs] - scale * vv[nt][0];
            float z1 = accO[nt][2 * rs + 1] - scale * vv[nt][1];
            zz[nt][0] = z0; zz[nt][1] = z1;
            zsq = fmaf(z0, z0, fmaf(z1, z1, zsq));
        }
        zsq = qsum(zsq);
        float ref_norm = fmaxf(sqrtf(ysq), sqrtf(vsq));
        float tol = FLT_EPSILON * 64.0f * ref_norm;
        bool zero_out = (vsq > 0.0f) && (sqrtf(zsq) <= tol);
        size_t zrow = (size_t)(b_ * SEQ + t) * 2048;
        #pragma unroll
        for (int nt = 0; nt < 8; nt++) {
            float z0 = zero_out ? 0.0f : zz[nt][0];
            float z1 = zero_out ? 0.0f : zz[nt][1];
            int c = h_ * 64 + dbase + nt * 8;
            size_t o = zrow + (c >> 5) * 64 + (c & 31);
            __nv_bfloat16 h0, l0b, h1, l1b;
            split2(z0, h0, l0b); split2(z1, h1, l1b);
            *(__nv_bfloat162*)(g_Zs2 + o) = __nv_bfloat162(h0, h1);
            *(__nv_bfloat162*)(g_Zs2 + o + 32) = __nv_bfloat162(l0b, l1b);
        }
    }
}

// ---------------------------------------------------------------------------
extern "C" void kernel_launch(void* const* d_in, const int* in_sizes, int n_in,
                              void* d_out, int out_size)
{
    const float* x  = (const float*)d_in[0];
    const float* Wq = (const float*)d_in[1];
    const float* Wk = (const float*)d_in[2];
    const float* Wv = (const float*)d_in[3];
    const float* Wo = (const float*)d_in[4];
    float* out = (float*)d_out;

    cudaFuncSetAttribute(gemm2s_kernel, cudaFuncAttributeMaxDynamicSharedMemorySize, GSMEM);
    cudaFuncSetAttribute(attn_mma_kernel, cudaFuncAttributeMaxDynamicSharedMemorySize, ASMEM);

    // all conversions in one launch: 4M (x) + 4*1M (weights) = 8M elements
    conv_all_kernel<<<(8 * 1024 * 1024) / 256, 256>>>(x, Wq, Wk, Wv, Wo);

    dim3 gqkv(3 * D_MODEL / BNg, ROWS / BMg);   // (24, 32)
    gemm2s_kernel<<<gqkv, 256, GSMEM>>>(nullptr, 0);

    dim3 gattn(NBH, SEQ / 128);                 // (32, 16)
    attn_mma_kernel<<<gattn, 256, ASMEM>>>();

    dim3 gout(D_MODEL / BNg, ROWS / BMg);       // (8, 32)
    gemm2s_kernel<<<gout, 256, GSMEM>>>(out, 1);
}

// round 14
// speedup vs baseline: 1.0472x; 1.0257x over previous
#include <cuda_runtime.h>
#include <cuda_bf16.h>
#include <math_constants.h>
#include <cfloat>
#include <cstdint>

#define D_MODEL 1024
#define NHEADS  16
#define DHEAD   64
#define BATCH   2
#define SEQ     2048
#define ROWS    (BATCH * SEQ)   // 4096
#define NBH     (BATCH * NHEADS)
#define QSCALE  0.18033688011112042f   // 0.125 * log2(e)

// 2-slot operands. GEMM A/B layout: [row][chunk32][hi 32 | lo 32], row stride 2048.
__device__ __nv_bfloat16 g_Xs2[ROWS * 2048];
__device__ __nv_bfloat16 g_Zs2[ROWS * 2048];
__device__ __nv_bfloat16 g_Wqkv2[3 * D_MODEL * 2048];
__device__ __nv_bfloat16 g_Wo2[D_MODEL * 2048];
// attention per-head panels: [bh][t][64]
__device__ __nv_bfloat16 g_Qh[NBH * SEQ * DHEAD];
__device__ __nv_bfloat16 g_Ql[NBH * SEQ * DHEAD];
__device__ __nv_bfloat16 g_Kh[NBH * SEQ * DHEAD];
__device__ __nv_bfloat16 g_Kl[NBH * SEQ * DHEAD];
__device__ __nv_bfloat16 g_Vh[NBH * SEQ * DHEAD];
__device__ __nv_bfloat16 g_Vl[NBH * SEQ * DHEAD];

// ---------------------------------------------------------------------------
// helpers
// ---------------------------------------------------------------------------
__device__ __forceinline__ uint32_t smem_u32(const void* p) {
    uint32_t a;
    asm("{ .reg .u64 t; cvta.to.shared.u64 t, %1; cvt.u32.u64 %0, t; }" : "=r"(a) : "l"(p));
    return a;
}
__device__ __forceinline__ void cp_async16(uint32_t dst, const void* src) {
    asm volatile("cp.async.cg.shared.global [%0], [%1], 16;" :: "r"(dst), "l"(src) : "memory");
}
__device__ __forceinline__ void cp_commit() {
    asm volatile("cp.async.commit_group;" ::: "memory");
}
__device__ __forceinline__ void cp_wait0() {
    asm volatile("cp.async.wait_group 0;" ::: "memory");
}
__device__ __forceinline__ void cp_wait1() {
    asm volatile("cp.async.wait_group 1;" ::: "memory");
}
__device__ __forceinline__ uint32_t sw128(uint32_t off) { return off ^ ((off >> 3) & 0x70); }
__device__ __forceinline__ void ldsm4(uint32_t& r0, uint32_t& r1, uint32_t& r2, uint32_t& r3,
                                      uint32_t addr) {
    asm volatile("ldmatrix.sync.aligned.m8n8.x4.shared.b16 {%0,%1,%2,%3}, [%4];"
                 : "=r"(r0), "=r"(r1), "=r"(r2), "=r"(r3) : "r"(addr));
}
__device__ __forceinline__ void ldsm4t(uint32_t& r0, uint32_t& r1, uint32_t& r2, uint32_t& r3,
                                       uint32_t addr) {
    asm volatile("ldmatrix.sync.aligned.m8n8.x4.trans.shared.b16 {%0,%1,%2,%3}, [%4];"
                 : "=r"(r0), "=r"(r1), "=r"(r2), "=r"(r3) : "r"(addr));
}
__device__ __forceinline__ void mma16816(float* c, const uint32_t* a, const uint32_t* b) {
    asm volatile(
        "mma.sync.aligned.m16n8k16.row.col.f32.bf16.bf16.f32 "
        "{%0,%1,%2,%3}, {%4,%5,%6,%7}, {%8,%9}, {%0,%1,%2,%3};"
        : "+f"(c[0]), "+f"(c[1]), "+f"(c[2]), "+f"(c[3])
        : "r"(a[0]), "r"(a[1]), "r"(a[2]), "r"(a[3]), "r"(b[0]), "r"(b[1]));
}
__device__ __forceinline__ float ex2f(float x) {
    float y; asm("ex2.approx.ftz.f32 %0, %1;" : "=f"(y) : "f"(x)); return y;
}
__device__ __forceinline__ uint32_t packbf(float hi, float lo) {
    uint32_t r; asm("cvt.rn.bf16x2.f32 %0, %1, %2;" : "=r"(r) : "f"(hi), "f"(lo)); return r;
}
__device__ __forceinline__ float qsum(float v) {
    v += __shfl_xor_sync(0xffffffffu, v, 1);
    v += __shfl_xor_sync(0xffffffffu, v, 2);
    return v;
}
__device__ __forceinline__ float qmax(float v) {
    v = fmaxf(v, __shfl_xor_sync(0xffffffffu, v, 1));
    v = fmaxf(v, __shfl_xor_sync(0xffffffffu, v, 2));
    return v;
}
__device__ __forceinline__ void split2(float x, __nv_bfloat16& h, __nv_bfloat16& l) {
    h = __float2bfloat16_rn(x);
    l = __float2bfloat16_rn(x - __bfloat162float(h));
}

// ---------------------------------------------------------------------------
// merged, vectorized conversion: 8M elements as 2M float4 groups.
// group g covers 4 consecutive c within one 32-chunk -> hi/lo each one 8B store.
// ---------------------------------------------------------------------------
__global__ void conv_all_kernel(const float* __restrict__ x,
                                const float* __restrict__ Wq,
                                const float* __restrict__ Wk,
                                const float* __restrict__ Wv,
                                const float* __restrict__ Wo)
{
    int g4 = blockIdx.x * blockDim.x + threadIdx.x;   // 0 .. 2M-1
    const int NX4 = (ROWS * D_MODEL) / 4;             // 1M
    const int NW4 = (D_MODEL * D_MODEL) / 4;          // 256K
    const float* src;
    __nv_bfloat16* dst;
    int i4;
    if (g4 < NX4) {
        src = x; dst = g_Xs2; i4 = g4;
    } else {
        int wi = g4 - NX4;
        int which = wi >> 18;                         // NW4 = 1<<18
        i4 = wi & (NW4 - 1);
        src = (which == 0) ? Wq : (which == 1) ? Wk : (which == 2) ? Wv : Wo;
        dst = (which < 3) ? (g_Wqkv2 + (size_t)which * D_MODEL * 2048) : g_Wo2;
    }
    int i = i4 * 4;
    int row = i >> 10, c = i & 1023;
    float4 v = *(const float4*)(src + i);
    __nv_bfloat16 h0, l0, h1, l1, h2, l2, h3, l3;
    split2(v.x, h0, l0); split2(v.y, h1, l1);
    split2(v.z, h2, l2); split2(v.w, h3, l3);
    size_t o = (size_t)row * 2048 + (c >> 5) * 64 + (c & 31);
    ((__nv_bfloat162*)(dst + o))[0]      = __nv_bfloat162(h0, h1);
    ((__nv_bfloat162*)(dst + o))[1]      = __nv_bfloat162(h2, h3);
    ((__nv_bfloat162*)(dst + o + 32))[0] = __nv_bfloat162(l0, l1);
    ((__nv_bfloat162*)(dst + o + 32))[1] = __nv_bfloat162(l2, l3);
}

// ---------------------------------------------------------------------------
// 2-slot HMMA GEMM (R11 mainloop). Grid axes swapped: blockIdx.x = M-block,
// blockIdx.y = N-block, so consecutive/co-resident CTAs share the same B
// (weight) tile -> better L2/L1 locality on the многократно re-read operand.
// ---------------------------------------------------------------------------
#define BMg 128
#define BNg 128
#define NCH 32
#define STA (BMg * 128)        // 16384
#define STB (BNg * 128)        // 16384
#define STAGE (STA + STB)      // 32768
#define GSMEM (3 * STAGE)      // 98304

__global__ void __launch_bounds__(256, 2)
gemm2s_kernel(float* __restrict__ outp, int mode)
{
    extern __shared__ char smem[];
    const uint32_t sbase = smem_u32(smem);
    const int tid = threadIdx.x;
    const int wid = tid >> 5;
    const int lane = tid & 31;
    const int wm = wid >> 2;
    const int wn = wid & 3;
    const int m0 = blockIdx.x * BMg;    // swapped
    const int n0 = blockIdx.y * BNg;    // swapped

    const __nv_bfloat16* A = (mode == 0) ? g_Xs2 : g_Zs2;
    const __nv_bfloat16* B = (mode == 0) ? g_Wqkv2 : g_Wo2;
    const __nv_bfloat16* Abase = A + (size_t)m0 * 2048;
    const __nv_bfloat16* Bbase = B + (size_t)n0 * 2048;

    auto fill = [&](int stage, int chunk) {
        uint32_t base = sbase + stage * STAGE;
        #pragma unroll
        for (int i = 0; i < 8; i++) {
            int g = i * 256 + tid;
            if (g < 1024) {
                int row = g >> 3, gr = g & 7;
                cp_async16(base + sw128((uint32_t)(row * 128 + gr * 16)),
                           Abase + (size_t)row * 2048 + chunk * 64 + gr * 8);
            } else {
                int bi = g - 1024;
                int row = bi >> 3, gr = bi & 7;
                cp_async16(base + STA + sw128((uint32_t)(row * 128 + gr * 16)),
                           Bbase + (size_t)row * 2048 + chunk * 64 + gr * 8);
            }
        }
    };

    float acc[4][4][4] = {};

    fill(0, 0); cp_commit();
    fill(1, 1); cp_commit();
    cp_wait1(); __syncthreads();

    for (int c = 0; c < NCH; c++) {
        if (c + 2 < NCH) fill((c + 2) % 3, c + 2);
        cp_commit();

        uint32_t abase = sbase + (c % 3) * STAGE;
        uint32_t bbase = abase + STA;

        #pragma unroll
        for (int s = 0; s < 2; s++) {
            const int kb = s * 32;
            uint32_t af[4][4];
            #pragma unroll
            for (int mt = 0; mt < 4; mt++) {
                int row = wm * 64 + mt * 16 + (lane & 15);
                ldsm4(af[mt][0], af[mt][1], af[mt][2], af[mt][3],
                      abase + sw128((uint32_t)(row * 128 + kb + (lane >> 4) * 16)));
            }
            uint32_t bh[4][2];
            #pragma unroll
            for (int bt = 0; bt < 2; bt++) {
                int row = wn * 32 + bt * 16 + (lane & 7) + ((lane >> 4) & 1) * 8;
                int col = kb + (((lane >> 3) & 1) * 16);
                ldsm4(bh[2 * bt][0], bh[2 * bt][1], bh[2 * bt + 1][0], bh[2 * bt + 1][1],
                      bbase + sw128((uint32_t)(row * 128 + col)));
            }
            #pragma unroll
            for (int mt = 0; mt < 4; mt++)
                #pragma unroll
                for (int nt = 0; nt < 4; nt++)
                    mma16816(acc[mt][nt], af[mt], bh[nt]);
            uint32_t bl[4][2];
            #pragma unroll
            for (int bt = 0; bt < 2; bt++) {
                int row = wn * 32 + bt * 16 + (lane & 7) + ((lane >> 4) & 1) * 8;
                int col = 64 + kb + (((lane >> 3) & 1) * 16);
                ldsm4(bl[2 * bt][0], bl[2 * bt][1], bl[2 * bt + 1][0], bl[2 * bt + 1][1],
                      bbase + sw128((uint32_t)(row * 128 + col)));
            }
            #pragma unroll
            for (int mt = 0; mt < 4; mt++)
                #pragma unroll
                for (int nt = 0; nt < 4; nt++)
                    mma16816(acc[mt][nt], af[mt], bl[nt]);
            #pragma unroll
            for (int mt = 0; mt < 4; mt++) {
                int row = wm * 64 + mt * 16 + (lane & 15);
                ldsm4(af[mt][0], af[mt][1], af[mt][2], af[mt][3],
                      abase + sw128((uint32_t)(row * 128 + 64 + kb + (lane >> 4) * 16)));
            }
            #pragma unroll
            for (int mt = 0; mt < 4; mt++)
                #pragma unroll
                for (int nt = 0; nt < 4; nt++)
                    mma16816(acc[mt][nt], af[mt], bh[nt]);
        }

        cp_wait1();
        __syncthreads();
    }

    const int gid = lane >> 2;
    const int tid2 = lane & 3;
    if (mode == 1) {
        #pragma unroll
        for (int mt = 0; mt < 4; mt++) {
            int row0 = m0 + wm * 64 + mt * 16 + gid;
            #pragma unroll
            for (int nt = 0; nt < 4; nt++) {
                int ncol = n0 + wn * 32 + nt * 8 + tid2 * 2;
                *(float2*)(outp + (size_t)row0 * 1024 + ncol) =
                    make_float2(acc[mt][nt][0], acc[mt][nt][1]);
                *(float2*)(outp + (size_t)(row0 + 8) * 1024 + ncol) =
                    make_float2(acc[mt][nt][2], acc[mt][nt][3]);
            }
        }
        return;
    }
    #pragma unroll
    for (int mt = 0; mt < 4; mt++) {
        int row0 = m0 + wm * 64 + mt * 16 + gid;
        #pragma unroll
        for (int nt = 0; nt < 4; nt++) {
            int ncol = n0 + wn * 32 + nt * 8 + tid2 * 2;
            int which = ncol >> 10;
            int c = ncol & 1023;
            int h = c >> 6, d = c & 63;
            __nv_bfloat16* hiA = (which == 0) ? g_Qh : (which == 1) ? g_Kh : g_Vh;
            __nv_bfloat16* loA = (which == 0) ? g_Ql : (which == 1) ? g_Kl : g_Vl;
            float sc = (which == 0) ? QSCALE : 1.0f;
            #pragma unroll
            for (int rr = 0; rr < 2; rr++) {
                int row = row0 + rr * 8;
                int b = row >> 11, t = row & 2047;
                size_t base = ((size_t)(b * NHEADS + h) * SEQ + t) * 64 + d;
                float v0 = acc[mt][nt][2 * rr] * sc;
                float v1 = acc[mt][nt][2 * rr + 1] * sc;
                __nv_bfloat16 h0, l0, h1, l1;
                split2(v0, h0, l0); split2(v1, h1, l1);
                *(__nv_bfloat162*)(hiA + base) = __nv_bfloat162(h0, h1);
                *(__nv_bfloat162*)(loA + base) = __nv_bfloat162(l0, l1);
            }
        }
    }
}

// ---------------------------------------------------------------------------
// 2-slot HMMA flash attention + exclusive output mod (R11 form — best measured)
// ---------------------------------------------------------------------------
#define AST 32768
#define ASMEM (3 * AST)          // 98304
#define NKV (SEQ / 64)           // 32

__global__ void __launch_bounds__(256, 2)
attn_mma_kernel()
{
    extern __shared__ char smem[];
    const uint32_t sb = smem_u32(smem);
    const int tid = threadIdx.x;
    const int wid = tid >> 5;       // 0..7
    const int lane = tid & 31;
    const int bh = blockIdx.x;
    const int q0 = blockIdx.y * 128;
    const int b_ = bh >> 4, h_ = bh & 15;

    const __nv_bfloat16* Qhs = g_Qh + ((size_t)bh * SEQ + q0) * 64;
    const __nv_bfloat16* Qls = g_Ql + ((size_t)bh * SEQ + q0) * 64;
    const __nv_bfloat16* Khs = g_Kh + (size_t)bh * SEQ * 64;
    const __nv_bfloat16* Kls = g_Kl + (size_t)bh * SEQ * 64;
    const __nv_bfloat16* Vhs = g_Vh + (size_t)bh * SEQ * 64;
    const __nv_bfloat16* Vls = g_Vl + (size_t)bh * SEQ * 64;

    #pragma unroll
    for (int i = 0; i < 8; i++) {
        int g = i * 256 + tid;
        int panel = g >> 10, idx = g & 1023;
        int row = idx >> 3, gr = idx & 7;
        const __nv_bfloat16* src = (panel ? Qls : Qhs) + (size_t)row * 64 + gr * 8;
        cp_async16(sb + 2 * AST + panel * 16384 + sw128((uint32_t)(row * 128 + gr * 16)), src);
    }
    cp_commit(); cp_wait0(); __syncthreads();

    uint32_t qh[4][4], ql[4][4];
    const int arow = wid * 16 + (lane & 15);
    #pragma unroll
    for (int s = 0; s < 4; s++) {
        const int cb = s * 32 + (lane >> 4) * 16;
        ldsm4(qh[s][0], qh[s][1], qh[s][2], qh[s][3],
              sb + 2 * AST + sw128((uint32_t)(arow * 128 + cb)));
        ldsm4(ql[s][0], ql[s][1], ql[s][2], ql[s][3],
              sb + 2 * AST + 16384 + sw128((uint32_t)(arow * 128 + cb)));
    }
    __syncthreads();

    auto fillKV = [&](int stage, int kt) {
        uint32_t base = sb + stage * AST;
        int t0 = kt * 64;
        #pragma unroll
        for (int i = 0; i < 8; i++) {
            int g = i * 256 + tid;
            int seg = g >> 9, idx = g & 511;
            int row = idx >> 3, gr = idx & 7;
            const __nv_bfloat16* src =
                (seg == 0) ? Khs : (seg == 1) ? Kls : (seg == 2) ? Vhs : Vls;
            cp_async16(base + seg * 8192 + sw128((uint32_t)(row * 128 + gr * 16)),
                       src + (size_t)(t0 + row) * 64 + gr * 8);
        }
    };

    fillKV(0, 0); cp_commit();
    fillKV(1, 1); cp_commit();
    cp_wait1(); __syncthreads();

    float accO[8][4] = {};
    float accS[8][4];
    float m0 = -CUDART_INF_F, m1 = -CUDART_INF_F;
    float l0 = 0.0f, l1 = 0.0f;

    for (int kt = 0; kt < NKV; kt++) {
        if (kt + 2 < NKV) fillKV((kt + 2) % 3, kt + 2);
        cp_commit();

        const uint32_t kb = sb + (kt % 3) * AST;
        const uint32_t klb = kb + 8192;

        #pragma unroll
        for (int nb = 0; nb < 4; nb++) {
            int row = nb * 16 + (lane & 7) + ((lane >> 4) & 1) * 8;
            float a0[4] = {}, a1[4] = {};
            #pragma unroll
            for (int s = 0; s < 4; s++) {
                int off = s * 32 + ((lane >> 3) & 1) * 16;
                uint32_t bhf[4], blf[4];
                ldsm4(bhf[0], bhf[1], bhf[2], bhf[3], kb + sw128((uint32_t)(row * 128 + off)));
                ldsm4(blf[0], blf[1], blf[2], blf[3], klb + sw128((uint32_t)(row * 128 + off)));
                mma16816(a0, qh[s], &bhf[0]);
                mma16816(a1, qh[s], &bhf[2]);
                mma16816(a0, qh[s], &blf[0]);
                mma16816(a1, qh[s], &blf[2]);
                mma16816(a0, ql[s], &bhf[0]);
                mma16816(a1, ql[s], &bhf[2]);
            }
            #pragma unroll
            for (int r = 0; r < 4; r++) { accS[2 * nb][r] = a0[r]; accS[2 * nb + 1][r] = a1[r]; }
        }

        float mx0 = -CUDART_INF_F, mx1 = -CUDART_INF_F;
        #pragma unroll
        for (int nt = 0; nt < 8; nt++) {
            mx0 = fmaxf(mx0, fmaxf(accS[nt][0], accS[nt][1]));
            mx1 = fmaxf(mx1, fmaxf(accS[nt][2], accS[nt][3]));
        }
        mx0 = qmax(mx0); mx1 = qmax(mx1);
        float m0n = fmaxf(m0, mx0), m1n = fmaxf(m1, mx1);
        float c0 = ex2f(m0 - m0n), c1 = ex2f(m1 - m1n);
        m0 = m0n; m1 = m1n;
        float s0 = 0.0f, s1 = 0.0f;
        #pragma unroll
        for (int nt = 0; nt < 8; nt++) {
            accS[nt][0] = ex2f(accS[nt][0] - m0);
            accS[nt][1] = ex2f(accS[nt][1] - m0);
            accS[nt][2] = ex2f(accS[nt][2] - m1);
            accS[nt][3] = ex2f(accS[nt][3] - m1);
            s0 += accS[nt][0] + accS[nt][1];
            s1 += accS[nt][2] + accS[nt][3];
            accO[nt][0] *= c0; accO[nt][1] *= c0;
            accO[nt][2] *= c1; accO[nt][3] *= c1;
        }
        l0 = l0 * c0 + qsum(s0);
        l1 = l1 * c1 + qsum(s1);

        const uint32_t vhb = kb + 16384, vlb = kb + 24576;
        #pragma unroll
        for (int j = 0; j < 4; j++) {
            uint32_t aPh[4], aPl[4];
            #pragma unroll
            for (int half = 0; half < 2; half++) {
                const float* a = accS[2 * j + half];
                uint32_t ph0 = packbf(a[1], a[0]);
                uint32_t ph1 = packbf(a[3], a[2]);
                float pl0e = a[0] - __uint_as_float(ph0 << 16);
                float pl0o = a[1] - __uint_as_float(ph0 & 0xffff0000u);
                float pl1e = a[2] - __uint_as_float(ph1 << 16);
                float pl1o = a[3] - __uint_as_float(ph1 & 0xffff0000u);
                aPh[2 * half]     = ph0;
                aPh[2 * half + 1] = ph1;
                aPl[2 * half]     = packbf(pl0o, pl0e);
                aPl[2 * half + 1] = packbf(pl1o, pl1e);
            }
            int vrow = j * 16 + ((lane >> 3) & 1) * 8 + (lane & 7);
            #pragma unroll
            for (int jc = 0; jc < 4; jc++) {
                int colb = (jc * 16 + ((lane >> 4) & 1) * 8) * 2;
                uint32_t vh[4], vl[4];
                ldsm4t(vh[0], vh[1], vh[2], vh[3],
                       vhb + sw128((uint32_t)(vrow * 128 + colb)));
                ldsm4t(vl[0], vl[1], vl[2], vl[3],
                       vlb + sw128((uint32_t)(vrow * 128 + colb)));
                mma16816(accO[2 * jc],     aPh, &vh[0]);
                mma16816(accO[2 * jc + 1], aPh, &vh[2]);
                mma16816(accO[2 * jc],     aPh, &vl[0]);
                mma16816(accO[2 * jc + 1], aPh, &vl[2]);
                mma16816(accO[2 * jc],     aPl, &vh[0]);
                mma16816(accO[2 * jc + 1], aPl, &vh[2]);
            }
        }

        cp_wait1();
        __syncthreads();
    }

    const float inv0 = 1.0f / l0, inv1 = 1.0f / l1;
    const int t_base = q0 + wid * 16 + (lane >> 2);
    const int dbase = (lane & 3) * 2;

    #pragma unroll
    for (int rs = 0; rs < 2; rs++) {
        int t = t_base + rs * 8;
        float inv = rs ? inv1 : inv0;
        float vv[8][2];
        float vsq = 0.0f, ydv = 0.0f, ysq = 0.0f;
        #pragma unroll
        for (int nt = 0; nt < 8; nt++) {
            size_t vb = ((size_t)bh * SEQ + t) * 64 + dbase + nt * 8;
            __nv_bfloat162 vh2 = *(const __nv_bfloat162*)(g_Vh + vb);
            __nv_bfloat162 vl2 = *(const __nv_bfloat162*)(g_Vl + vb);
            float vx = __bfloat162float(vh2.x) + __bfloat162float(vl2.x);
            float vy = __bfloat162float(vh2.y) + __bfloat162float(vl2.y);
            vv[nt][0] = vx; vv[nt][1] = vy;
            float y0 = accO[nt][2 * rs] * inv;
            float y1 = accO[nt][2 * rs + 1] * inv;
            accO[nt][2 * rs] = y0; accO[nt][2 * rs + 1] = y1;
            vsq = fmaf(vx, vx, fmaf(vy, vy, vsq));
            ydv = fmaf(y0, vx, fmaf(y1, vy, ydv));
            ysq = fmaf(y0, y0, fmaf(y1, y1, ysq));
        }
        vsq = qsum(vsq); ydv = qsum(ydv); ysq = qsum(ysq);
        float scale = (vsq > 0.0f) ? (ydv / fmaxf(vsq, FLT_MIN)) : 0.0f;
        float zsq = 0.0f;
        float zz[8][2];
        #pragma unroll
        for (int nt = 0; nt < 8; nt++) {
            float z0 = accO[nt][2 * rs] - scale * vv[nt][0];
            float z1 = accO[nt][2 * rs + 1] - scale * vv[nt][1];
            zz[nt][0] = z0; zz[nt][1] = z1;
            zsq = fmaf(z0, z0, fmaf(z1, z1, zsq));
        }
        zsq = qsum(zsq);
        float ref_norm = fmaxf(sqrtf(ysq), sqrtf(vsq));
        float tol = FLT_EPSILON * 64.0f * ref_norm;
        bool zero_out = (vsq > 0.0f) && (sqrtf(zsq) <= tol);
        size_t zrow = (size_t)(b_ * SEQ + t) * 2048;
        #pragma unroll
        for (int nt = 0; nt < 8; nt++) {
            float z0 = zero_out ? 0.0f : zz[nt][0];
            float z1 = zero_out ? 0.0f : zz[nt][1];
            int c = h_ * 64 + dbase + nt * 8;
            size_t o = zrow + (c >> 5) * 64 + (c & 31);
            __nv_bfloat16 h0, l0b, h1, l1b;
            split2(z0, h0, l0b); split2(z1, h1, l1b);
            *(__nv_bfloat162*)(g_Zs2 + o) = __nv_bfloat162(h0, h1);
            *(__nv_bfloat162*)(g_Zs2 + o + 32) = __nv_bfloat162(l0b, l1b);
        }
    }
}

// ---------------------------------------------------------------------------
extern "C" void kernel_launch(void* const* d_in, const int* in_sizes, int n_in,
                              void* d_out, int out_size)
{
    const float* x  = (const float*)d_in[0];
    const float* Wq = (const float*)d_in[1];
    const float* Wk = (const float*)d_in[2];
    const float* Wv = (const float*)d_in[3];
    const float* Wo = (const float*)d_in[4];
    float* out = (float*)d_out;

    cudaFuncSetAttribute(gemm2s_kernel, cudaFuncAttributeMaxDynamicSharedMemorySize, GSMEM);
    cudaFuncSetAttribute(attn_mma_kernel, cudaFuncAttributeMaxDynamicSharedMemorySize, ASMEM);

    // all conversions, vectorized x4: 2M threads
    conv_all_kernel<<<(2 * 1024 * 1024) / 256, 256>>>(x, Wq, Wk, Wv, Wo);

    // grids swapped to match swapped block-index mapping (x=M, y=N)
    dim3 gqkv(ROWS / BMg, 3 * D_MODEL / BNg);   // (32, 24)
    gemm2s_kernel<<<gqkv, 256, GSMEM>>>(nullptr, 0);

    dim3 gattn(NBH, SEQ / 128);                 // (32, 16)
    attn_mma_kernel<<<gattn, 256, ASMEM>>>();

    dim3 gout(ROWS / BMg, D_MODEL / BNg);       // (32, 8)
    gemm2s_kernel<<<gout, 256, GSMEM>>>(out, 1);
}